// round 14
// baseline (speedup 1.0000x reference)
#include <cuda_runtime.h>
#include <cuda_bf16.h>
#include <cstdint>

#define NV 50000
#define H 128
#define NTILE 391                  // ceil(NV/128)
#define NGEMM (2 * NTILE)          // 782 GEMM blocks (half0 + half1)

// Scratch (no cudaMalloc allowed)
__device__ float g_y1[(size_t)NV * H];   // 25.6 MB, x @ W1^T
__device__ int   g_cnt[NV];              // degree
__device__ int   g_flag1[NTILE];         // y1 tile ready
__device__ int   g_flag2[NTILE];         // out tile initialized
__device__ int   g_done;                 // completed GEMM blocks

// ---------------------------------------------------------------------------
// 1. zero counters + flags
// ---------------------------------------------------------------------------
__global__ void k_zero() {
    int i = blockIdx.x * blockDim.x + threadIdx.x;
    if (i < NV) g_cnt[i] = 0;
    if (i < NTILE) { g_flag1[i] = 0; g_flag2[i] = 0; }
    if (i == 0) g_done = 0;
}

// ---------------------------------------------------------------------------
// 2. degree histogram: every element of edge_idx is a dst exactly once
// ---------------------------------------------------------------------------
__global__ void k_hist(const int* __restrict__ ei, int total) {
    int i = blockIdx.x * blockDim.x + threadIdx.x;
    int i4 = i * 4;
    if (i4 + 3 < total) {
        int4 v = *reinterpret_cast<const int4*>(ei + i4);
        atomicAdd(&g_cnt[v.x], 1);
        atomicAdd(&g_cnt[v.y], 1);
        atomicAdd(&g_cnt[v.z], 1);
        atomicAdd(&g_cnt[v.w], 1);
    } else {
        for (int j = i4; j < total; j++) atomicAdd(&g_cnt[ei[j]], 1);
    }
}

// ---------------------------------------------------------------------------
// helpers
// ---------------------------------------------------------------------------
#define BK 32
#define PITCH 40

__device__ __forceinline__ void mma_16816(float* c, const uint32_t* a,
                                          uint32_t b0, uint32_t b1) {
    asm volatile(
        "mma.sync.aligned.m16n8k16.row.col.f32.bf16.bf16.f32 "
        "{%0,%1,%2,%3}, {%4,%5,%6,%7}, {%8,%9}, {%0,%1,%2,%3};"
        : "+f"(c[0]), "+f"(c[1]), "+f"(c[2]), "+f"(c[3])
        : "r"(a[0]), "r"(a[1]), "r"(a[2]), "r"(a[3]), "r"(b0), "r"(b1));
}

#define LDSM_X4(r0, r1, r2, r3, addr) \
    asm volatile("ldmatrix.sync.aligned.m8n8.x4.shared.b16 {%0,%1,%2,%3}, [%4];" \
                 : "=r"(r0), "=r"(r1), "=r"(r2), "=r"(r3) : "r"(addr))

__device__ __forceinline__ int ld_acq(const int* p) {
    int v;
    asm volatile("ld.acquire.gpu.global.b32 %0, [%1];" : "=r"(v) : "l"(p) : "memory");
    return v;
}

__device__ __forceinline__ void wait_flag(const int* p) {
    while (ld_acq(p) == 0) __nanosleep(64);
}

// ---------------------------------------------------------------------------
// 3. FUSED kernel: blocks [0, NGEMM) compute GEMM tiles and publish flags;
//    blocks >= NGEMM scatter edges (waiting on the tiles they need).
//    GEMM blocks come FIRST in the grid -> no deadlock: scatter blocks only
//    occupy SMs after GEMM blocks are already resident/retired.
// ---------------------------------------------------------------------------
__global__ __launch_bounds__(256, 2)
void k_fused(const float* __restrict__ x, const float* __restrict__ W,
             const int* __restrict__ ei, float* __restrict__ out, int nE) {
    const int bid = blockIdx.x;
    const int tid = threadIdx.x;

    if (bid < NGEMM) {
        // ===================== GEMM tile (R12-proven) =====================
        __shared__ __align__(16) __nv_bfloat16 Ahi[128][PITCH];
        __shared__ __align__(16) __nv_bfloat16 Alo[128][PITCH];
        __shared__ __align__(16) __nv_bfloat16 Bhi[128][PITCH];
        __shared__ __align__(16) __nv_bfloat16 Blo[128][PITCH];

        const int half   = (bid >= NTILE) ? 1 : 0;
        const int rtile  = bid - half * NTILE;
        const int row0   = rtile * 128;
        const int ncol0  = half * 128;

        const int wid    = tid >> 5;
        const int lane   = tid & 31;
        const int grp    = lane >> 2;
        const int tig    = lane & 3;
        const int warp_m = wid & 3;
        const int warp_n = wid >> 2;

        const uint32_t sAhi = (uint32_t)__cvta_generic_to_shared(&Ahi[0][0]);
        const uint32_t sAlo = (uint32_t)__cvta_generic_to_shared(&Alo[0][0]);
        const uint32_t sBhi = (uint32_t)__cvta_generic_to_shared(&Bhi[0][0]);
        const uint32_t sBlo = (uint32_t)__cvta_generic_to_shared(&Blo[0][0]);

        const int a_row16 = (lane & 7) + ((lane >> 3) & 1) * 8;
        const int a_k8    = ((lane >> 4) & 1) * 8;
        const uint32_t aoff = (uint32_t)(((warp_m * 32 + a_row16) * PITCH + a_k8) * 2);
        const int b_row16 = (lane & 7) + ((lane >> 4) & 1) * 8;
        const int b_k8    = ((lane >> 3) & 1) * 8;
        const uint32_t boff = (uint32_t)(((warp_n * 64 + b_row16) * PITCH + b_k8) * 2);

        float acc[2][8][4];
#pragma unroll
        for (int mi = 0; mi < 2; mi++)
#pragma unroll
            for (int ni = 0; ni < 8; ni++)
#pragma unroll
                for (int q = 0; q < 4; q++) acc[mi][ni][q] = 0.0f;

        for (int kt = 0; kt < 4; kt++) {
            __syncthreads();
#pragma unroll
            for (int p = 0; p < 4; p++) {
                int idx  = p * 256 + tid;
                int row  = idx >> 3;
                int colq = idx & 7;
                int grow = row0 + row;
                float4 v = make_float4(0.f, 0.f, 0.f, 0.f);
                if (grow < NV)
                    v = *reinterpret_cast<const float4*>(
                        x + (size_t)grow * H + kt * BK + colq * 4);
                uint32_t bx = __float_as_uint(v.x), by = __float_as_uint(v.y);
                uint32_t bz = __float_as_uint(v.z), bw = __float_as_uint(v.w);
                uint32_t hp0 = __byte_perm(bx, by, 0x7632);
                uint32_t hp1 = __byte_perm(bz, bw, 0x7632);
                float lx = v.x - __uint_as_float(bx & 0xFFFF0000u);
                float ly = v.y - __uint_as_float(by & 0xFFFF0000u);
                float lz = v.z - __uint_as_float(bz & 0xFFFF0000u);
                float lw = v.w - __uint_as_float(bw & 0xFFFF0000u);
                __nv_bfloat162 l0 = __floats2bfloat162_rn(lx, ly);
                __nv_bfloat162 l1 = __floats2bfloat162_rn(lz, lw);
                *reinterpret_cast<uint2*>(&Ahi[row][colq * 4]) = make_uint2(hp0, hp1);
                *reinterpret_cast<uint2*>(&Alo[row][colq * 4]) =
                    make_uint2(*reinterpret_cast<uint32_t*>(&l0),
                               *reinterpret_cast<uint32_t*>(&l1));
            }
#pragma unroll
            for (int p = 0; p < 4; p++) {
                int idx  = p * 256 + tid;
                int n    = idx >> 3;
                int colq = idx & 7;
                float4 v = *reinterpret_cast<const float4*>(
                    W + (size_t)n * (2 * H) + ncol0 + kt * BK + colq * 4);
                uint32_t bx = __float_as_uint(v.x), by = __float_as_uint(v.y);
                uint32_t bz = __float_as_uint(v.z), bw = __float_as_uint(v.w);
                uint32_t hp0 = __byte_perm(bx, by, 0x7632);
                uint32_t hp1 = __byte_perm(bz, bw, 0x7632);
                float lx = v.x - __uint_as_float(bx & 0xFFFF0000u);
                float ly = v.y - __uint_as_float(by & 0xFFFF0000u);
                float lz = v.z - __uint_as_float(bz & 0xFFFF0000u);
                float lw = v.w - __uint_as_float(bw & 0xFFFF0000u);
                __nv_bfloat162 l0 = __floats2bfloat162_rn(lx, ly);
                __nv_bfloat162 l1 = __floats2bfloat162_rn(lz, lw);
                *reinterpret_cast<uint2*>(&Bhi[n][colq * 4]) = make_uint2(hp0, hp1);
                *reinterpret_cast<uint2*>(&Blo[n][colq * 4]) =
                    make_uint2(*reinterpret_cast<uint32_t*>(&l0),
                               *reinterpret_cast<uint32_t*>(&l1));
            }
            __syncthreads();

#pragma unroll
            for (int ks = 0; ks < 2; ks++) {
                const uint32_t koff = (uint32_t)(ks * 16 * 2);
                uint32_t ah[2][4], al[2][4];
#pragma unroll
                for (int mi = 0; mi < 2; mi++) {
                    uint32_t ao = aoff + (uint32_t)(mi * 16 * PITCH * 2) + koff;
                    LDSM_X4(ah[mi][0], ah[mi][1], ah[mi][2], ah[mi][3], sAhi + ao);
                    LDSM_X4(al[mi][0], al[mi][1], al[mi][2], al[mi][3], sAlo + ao);
                }
                uint32_t bh[8][2], bl[8][2];
#pragma unroll
                for (int pr = 0; pr < 4; pr++) {
                    uint32_t bo = boff + (uint32_t)(pr * 16 * PITCH * 2) + koff;
                    LDSM_X4(bh[pr * 2][0], bh[pr * 2][1],
                            bh[pr * 2 + 1][0], bh[pr * 2 + 1][1], sBhi + bo);
                    LDSM_X4(bl[pr * 2][0], bl[pr * 2][1],
                            bl[pr * 2 + 1][0], bl[pr * 2 + 1][1], sBlo + bo);
                }
#pragma unroll
                for (int ni = 0; ni < 8; ni++) {
#pragma unroll
                    for (int mi = 0; mi < 2; mi++) {
                        mma_16816(acc[mi][ni], ah[mi], bh[ni][0], bh[ni][1]);
                        mma_16816(acc[mi][ni], ah[mi], bl[ni][0], bl[ni][1]);
                        mma_16816(acc[mi][ni], al[mi], bh[ni][0], bh[ni][1]);
                    }
                }
            }
        }

        // ---- epilogue ----
        float* dst = half ? out : g_y1;
#pragma unroll
        for (int mi = 0; mi < 2; mi++) {
            int r0 = row0 + warp_m * 32 + mi * 16 + grp;
            float dg0 = 1.0f, dg1 = 1.0f;
            if (half) {
                if (r0 < NV)     dg0 = (float)g_cnt[r0];
                if (r0 + 8 < NV) dg1 = (float)g_cnt[r0 + 8];
            }
#pragma unroll
            for (int ni = 0; ni < 8; ni++) {
                int col = warp_n * 64 + ni * 8 + tig * 2;
                if (r0 < NV)
                    *reinterpret_cast<float2*>(dst + (size_t)r0 * H + col) =
                        make_float2(acc[mi][ni][0] * dg0, acc[mi][ni][1] * dg0);
                if (r0 + 8 < NV)
                    *reinterpret_cast<float2*>(dst + (size_t)(r0 + 8) * H + col) =
                        make_float2(acc[mi][ni][2] * dg1, acc[mi][ni][3] * dg1);
            }
        }

        // ---- publish tile ----
        __syncthreads();
        if (tid == 0) {
            __threadfence();
            int* flag = half ? &g_flag2[rtile] : &g_flag1[rtile];
            atomicExch(flag, 1);
            atomicAdd(&g_done, 1);
        }
    } else {
        // ================= scatter chunk: 8 warps x 8 edges =================
        const int sb   = bid - NGEMM;
        const int wid  = tid >> 5;
        const int lane = tid & 31;
        const int base = sb * 64 + wid * 8;
        const int twoE = 2 * nE;

        bool all = (ld_acq(&g_done) >= NGEMM);

#pragma unroll 1
        for (int q = 0; q < 8; q++) {
            int t = base + q;
            if (t >= twoE) break;
            int s, d;
            if (t < nE) { s = ei[t]; d = ei[nE + t]; }
            else        { int e = t - nE; s = ei[nE + e]; d = ei[e]; }
            if (!all) {
                wait_flag(&g_flag1[s >> 7]);
                wait_flag(&g_flag2[d >> 7]);
            }
            float4 v = reinterpret_cast<const float4*>(g_y1 + (size_t)s * H)[lane];
            float4* o = reinterpret_cast<float4*>(out + (size_t)d * H) + lane;
            asm volatile("red.global.add.v4.f32 [%0], {%1, %2, %3, %4};"
                         :: "l"(o), "f"(v.x), "f"(v.y), "f"(v.z), "f"(v.w)
                         : "memory");
        }
    }
}

// ---------------------------------------------------------------------------
extern "C" void kernel_launch(void* const* d_in, const int* in_sizes, int n_in,
                              void* d_out, int out_size) {
    const float* x  = (const float*)d_in[0];   // [NV, 128] f32
    const float* W  = (const float*)d_in[1];   // [128, 256] f32
    const int*   ei = (const int*)d_in[2];     // [2, E] i32
    float* out = (float*)d_out;                // [NV, 128] f32

    int nE    = in_sizes[2] / 2;
    int total = in_sizes[2];

    k_zero<<<(NV + 255) / 256, 256>>>();
    k_hist<<<(total / 4 + 255) / 256, 256>>>(ei, total);

    int scat_blocks = (2 * nE + 63) / 64;      // 8 warps x 8 edges each
    k_fused<<<NGEMM + scat_blocks, 256>>>(x, W, ei, out, nE);

    (void)n_in; (void)out_size;
}

// round 15
// speedup vs baseline: 1.5024x; 1.5024x over previous
#include <cuda_runtime.h>
#include <cuda_bf16.h>
#include <cstdint>

#define NV 50000
#define NE_MAX 400000
#define H 128

// Scratch (no cudaMalloc allowed)
__device__ float g_y1[(size_t)NV * H];   // 25.6 MB, x @ W1^T
__device__ int   g_cnt[NV];              // degree
__device__ int   g_rowptr[NV + 1];
__device__ int   g_cursor[NV];
__device__ int   g_src[2 * NE_MAX];      // dst-sorted src list
__device__ int   g_dst[2 * NE_MAX];      // dst per sorted position

// ---------------------------------------------------------------------------
// 1. zero degree counters
// ---------------------------------------------------------------------------
__global__ void k_zero_cnt() {
    int i = blockIdx.x * blockDim.x + threadIdx.x;
    if (i < NV) g_cnt[i] = 0;
}

// ---------------------------------------------------------------------------
// 2. degree histogram: every element of edge_idx is a dst exactly once
// ---------------------------------------------------------------------------
__global__ void k_hist(const int* __restrict__ ei, int total) {
    int i = blockIdx.x * blockDim.x + threadIdx.x;
    int i4 = i * 4;
    if (i4 + 3 < total) {
        int4 v = *reinterpret_cast<const int4*>(ei + i4);
        atomicAdd(&g_cnt[v.x], 1);
        atomicAdd(&g_cnt[v.y], 1);
        atomicAdd(&g_cnt[v.z], 1);
        atomicAdd(&g_cnt[v.w], 1);
    } else {
        for (int j = i4; j < total; j++) atomicAdd(&g_cnt[ei[j]], 1);
    }
}

// ---------------------------------------------------------------------------
// 3. exclusive scan over 50k counts (proven R5 kernel)
// ---------------------------------------------------------------------------
#define SCAN_CH 49   // 1024 * 49 = 50176 >= NV
__global__ __launch_bounds__(1024)
void k_scan() {
    __shared__ int ssum[1024];
    int t = threadIdx.x;
    int base = t * SCAN_CH;

    int s = 0;
#pragma unroll 4
    for (int i = 0; i < SCAN_CH; i++) {
        int idx = base + i;
        if (idx < NV) s += g_cnt[idx];
    }
    ssum[t] = s;
    __syncthreads();
    for (int off = 1; off < 1024; off <<= 1) {
        int v = (t >= off) ? ssum[t - off] : 0;
        __syncthreads();
        ssum[t] += v;
        __syncthreads();
    }
    int run = ssum[t] - s;
    for (int i = 0; i < SCAN_CH; i++) {
        int idx = base + i;
        if (idx < NV) {
            int c = g_cnt[idx];
            g_rowptr[idx] = run;
            g_cursor[idx] = run;
            run += c;
        }
    }
    if (t == 1023) g_rowptr[NV] = ssum[1023];
}

// ---------------------------------------------------------------------------
// 4. fill: one thread per DIRECTED edge, 1 atomic, store (src, dst)
// ---------------------------------------------------------------------------
__global__ void k_fill(const int* __restrict__ ei, int nE) {
    int t = blockIdx.x * blockDim.x + threadIdx.x;
    if (t >= 2 * nE) return;
    int src, dst;
    if (t < nE) { src = ei[t]; dst = ei[nE + t]; }
    else        { int e = t - nE; src = ei[nE + e]; dst = ei[e]; }
    int p = atomicAdd(&g_cursor[dst], 1);
    g_src[p] = src;
    g_dst[p] = dst;
}

// ---------------------------------------------------------------------------
// 5. HMMA GEMM (R12-proven, unchanged): Y[M,256] = x @ Wcat^T
//    half 0 -> g_y1, half 1 -> out scaled by deg
// ---------------------------------------------------------------------------
#define BK 32
#define PITCH 40

__device__ __forceinline__ void mma_16816(float* c, const uint32_t* a,
                                          uint32_t b0, uint32_t b1) {
    asm volatile(
        "mma.sync.aligned.m16n8k16.row.col.f32.bf16.bf16.f32 "
        "{%0,%1,%2,%3}, {%4,%5,%6,%7}, {%8,%9}, {%0,%1,%2,%3};"
        : "+f"(c[0]), "+f"(c[1]), "+f"(c[2]), "+f"(c[3])
        : "r"(a[0]), "r"(a[1]), "r"(a[2]), "r"(a[3]), "r"(b0), "r"(b1));
}

#define LDSM_X4(r0, r1, r2, r3, addr) \
    asm volatile("ldmatrix.sync.aligned.m8n8.x4.shared.b16 {%0,%1,%2,%3}, [%4];" \
                 : "=r"(r0), "=r"(r1), "=r"(r2), "=r"(r3) : "r"(addr))

__global__ __launch_bounds__(256)
void k_gemm(const float* __restrict__ x, const float* __restrict__ W,
            float* __restrict__ out) {
    __shared__ __align__(16) __nv_bfloat16 Ahi[128][PITCH];
    __shared__ __align__(16) __nv_bfloat16 Alo[128][PITCH];
    __shared__ __align__(16) __nv_bfloat16 Bhi[128][PITCH];
    __shared__ __align__(16) __nv_bfloat16 Blo[128][PITCH];

    const int tid    = threadIdx.x;
    const int wid    = tid >> 5;
    const int lane   = tid & 31;
    const int grp    = lane >> 2;
    const int tig    = lane & 3;
    const int warp_m = wid & 3;
    const int warp_n = wid >> 2;
    const int row0   = blockIdx.x * 128;
    const int ncol0  = blockIdx.y * 128;

    const uint32_t sAhi = (uint32_t)__cvta_generic_to_shared(&Ahi[0][0]);
    const uint32_t sAlo = (uint32_t)__cvta_generic_to_shared(&Alo[0][0]);
    const uint32_t sBhi = (uint32_t)__cvta_generic_to_shared(&Bhi[0][0]);
    const uint32_t sBlo = (uint32_t)__cvta_generic_to_shared(&Blo[0][0]);

    const int a_row16 = (lane & 7) + ((lane >> 3) & 1) * 8;
    const int a_k8    = ((lane >> 4) & 1) * 8;
    const uint32_t aoff = (uint32_t)(((warp_m * 32 + a_row16) * PITCH + a_k8) * 2);
    const int b_row16 = (lane & 7) + ((lane >> 4) & 1) * 8;
    const int b_k8    = ((lane >> 3) & 1) * 8;
    const uint32_t boff = (uint32_t)(((warp_n * 64 + b_row16) * PITCH + b_k8) * 2);

    float acc[2][8][4];
#pragma unroll
    for (int mi = 0; mi < 2; mi++)
#pragma unroll
        for (int ni = 0; ni < 8; ni++)
#pragma unroll
            for (int q = 0; q < 4; q++) acc[mi][ni][q] = 0.0f;

    for (int kt = 0; kt < 4; kt++) {
        __syncthreads();
#pragma unroll
        for (int p = 0; p < 4; p++) {
            int idx  = p * 256 + tid;
            int row  = idx >> 3;
            int colq = idx & 7;
            int grow = row0 + row;
            float4 v = make_float4(0.f, 0.f, 0.f, 0.f);
            if (grow < NV)
                v = *reinterpret_cast<const float4*>(
                    x + (size_t)grow * H + kt * BK + colq * 4);
            uint32_t bx = __float_as_uint(v.x), by = __float_as_uint(v.y);
            uint32_t bz = __float_as_uint(v.z), bw = __float_as_uint(v.w);
            uint32_t hp0 = __byte_perm(bx, by, 0x7632);
            uint32_t hp1 = __byte_perm(bz, bw, 0x7632);
            float lx = v.x - __uint_as_float(bx & 0xFFFF0000u);
            float ly = v.y - __uint_as_float(by & 0xFFFF0000u);
            float lz = v.z - __uint_as_float(bz & 0xFFFF0000u);
            float lw = v.w - __uint_as_float(bw & 0xFFFF0000u);
            __nv_bfloat162 l0 = __floats2bfloat162_rn(lx, ly);
            __nv_bfloat162 l1 = __floats2bfloat162_rn(lz, lw);
            *reinterpret_cast<uint2*>(&Ahi[row][colq * 4]) = make_uint2(hp0, hp1);
            *reinterpret_cast<uint2*>(&Alo[row][colq * 4]) =
                make_uint2(*reinterpret_cast<uint32_t*>(&l0),
                           *reinterpret_cast<uint32_t*>(&l1));
        }
#pragma unroll
        for (int p = 0; p < 4; p++) {
            int idx  = p * 256 + tid;
            int n    = idx >> 3;
            int colq = idx & 7;
            float4 v = *reinterpret_cast<const float4*>(
                W + (size_t)n * (2 * H) + ncol0 + kt * BK + colq * 4);
            uint32_t bx = __float_as_uint(v.x), by = __float_as_uint(v.y);
            uint32_t bz = __float_as_uint(v.z), bw = __float_as_uint(v.w);
            uint32_t hp0 = __byte_perm(bx, by, 0x7632);
            uint32_t hp1 = __byte_perm(bz, bw, 0x7632);
            float lx = v.x - __uint_as_float(bx & 0xFFFF0000u);
            float ly = v.y - __uint_as_float(by & 0xFFFF0000u);
            float lz = v.z - __uint_as_float(bz & 0xFFFF0000u);
            float lw = v.w - __uint_as_float(bw & 0xFFFF0000u);
            __nv_bfloat162 l0 = __floats2bfloat162_rn(lx, ly);
            __nv_bfloat162 l1 = __floats2bfloat162_rn(lz, lw);
            *reinterpret_cast<uint2*>(&Bhi[n][colq * 4]) = make_uint2(hp0, hp1);
            *reinterpret_cast<uint2*>(&Blo[n][colq * 4]) =
                make_uint2(*reinterpret_cast<uint32_t*>(&l0),
                           *reinterpret_cast<uint32_t*>(&l1));
        }
        __syncthreads();

#pragma unroll
        for (int ks = 0; ks < 2; ks++) {
            const uint32_t koff = (uint32_t)(ks * 16 * 2);
            uint32_t ah[2][4], al[2][4];
#pragma unroll
            for (int mi = 0; mi < 2; mi++) {
                uint32_t ao = aoff + (uint32_t)(mi * 16 * PITCH * 2) + koff;
                LDSM_X4(ah[mi][0], ah[mi][1], ah[mi][2], ah[mi][3], sAhi + ao);
                LDSM_X4(al[mi][0], al[mi][1], al[mi][2], al[mi][3], sAlo + ao);
            }
            uint32_t bh[8][2], bl[8][2];
#pragma unroll
            for (int pr = 0; pr < 4; pr++) {
                uint32_t bo = boff + (uint32_t)(pr * 16 * PITCH * 2) + koff;
                LDSM_X4(bh[pr * 2][0], bh[pr * 2][1],
                        bh[pr * 2 + 1][0], bh[pr * 2 + 1][1], sBhi + bo);
                LDSM_X4(bl[pr * 2][0], bl[pr * 2][1],
                        bl[pr * 2 + 1][0], bl[pr * 2 + 1][1], sBlo + bo);
            }
#pragma unroll
            for (int ni = 0; ni < 8; ni++) {
#pragma unroll
                for (int mi = 0; mi < 2; mi++) {
                    mma_16816(acc[mi][ni], ah[mi], bh[ni][0], bh[ni][1]);
                    mma_16816(acc[mi][ni], ah[mi], bl[ni][0], bl[ni][1]);
                    mma_16816(acc[mi][ni], al[mi], bh[ni][0], bh[ni][1]);
                }
            }
        }
    }

    const bool to_out = (blockIdx.y == 1);
    float* dst = to_out ? out : g_y1;
#pragma unroll
    for (int mi = 0; mi < 2; mi++) {
        int r0 = row0 + warp_m * 32 + mi * 16 + grp;
        float dg0 = 1.0f, dg1 = 1.0f;
        if (to_out) {
            if (r0 < NV)     dg0 = (float)g_cnt[r0];
            if (r0 + 8 < NV) dg1 = (float)g_cnt[r0 + 8];
        }
#pragma unroll
        for (int ni = 0; ni < 8; ni++) {
            int col = warp_n * 64 + ni * 8 + tig * 2;
            if (r0 < NV)
                *reinterpret_cast<float2*>(dst + (size_t)r0 * H + col) =
                    make_float2(acc[mi][ni][0] * dg0, acc[mi][ni][1] * dg0);
            if (r0 + 8 < NV)
                *reinterpret_cast<float2*>(dst + (size_t)(r0 + 8) * H + col) =
                    make_float2(acc[mi][ni][2] * dg1, acc[mi][ni][3] * dg1);
        }
    }
}

// ---------------------------------------------------------------------------
// 6. segmented scatter: warp per 8 dst-SORTED edges. Prefetch 8 independent
//    y1 rows (full MLP), accumulate equal-dst runs in registers, RED only at
//    run boundaries -> ~5x fewer RED ops than warp-per-edge.
// ---------------------------------------------------------------------------
__global__ __launch_bounds__(256)
void k_scat_seg(float* __restrict__ out, int twoE) {
    int gw   = (int)(((unsigned)blockIdx.x * blockDim.x + threadIdx.x) >> 5);
    int lane = threadIdx.x & 31;
    int base = gw * 8;
    if (base >= twoE) return;
    int n = min(8, twoE - base);

    int src[8], dst[8];
    if (n == 8) {
        int4 s0 = *reinterpret_cast<const int4*>(g_src + base);
        int4 s1 = *reinterpret_cast<const int4*>(g_src + base + 4);
        int4 d0 = *reinterpret_cast<const int4*>(g_dst + base);
        int4 d1 = *reinterpret_cast<const int4*>(g_dst + base + 4);
        src[0]=s0.x; src[1]=s0.y; src[2]=s0.z; src[3]=s0.w;
        src[4]=s1.x; src[5]=s1.y; src[6]=s1.z; src[7]=s1.w;
        dst[0]=d0.x; dst[1]=d0.y; dst[2]=d0.z; dst[3]=d0.w;
        dst[4]=d1.x; dst[5]=d1.y; dst[6]=d1.z; dst[7]=d1.w;
    } else {
        for (int q = 0; q < n; q++) {
            src[q] = g_src[base + q];
            dst[q] = g_dst[base + q];
        }
    }

    // prefetch all rows -> 8 independent LDG.128 in flight
    float4 v[8];
#pragma unroll
    for (int q = 0; q < 8; q++)
        if (q < n)
            v[q] = __ldg(reinterpret_cast<const float4*>(
                       g_y1 + (size_t)src[q] * H) + lane);

    float4 acc = v[0];
    int curd = dst[0];
#pragma unroll
    for (int q = 1; q < 8; q++) {
        if (q >= n) break;
        if (dst[q] != curd) {
            float4* o = reinterpret_cast<float4*>(out + (size_t)curd * H) + lane;
            asm volatile("red.global.add.v4.f32 [%0], {%1, %2, %3, %4};"
                         :: "l"(o), "f"(acc.x), "f"(acc.y), "f"(acc.z), "f"(acc.w)
                         : "memory");
            acc = v[q];
            curd = dst[q];
        } else {
            acc.x += v[q].x; acc.y += v[q].y;
            acc.z += v[q].z; acc.w += v[q].w;
        }
    }
    {
        float4* o = reinterpret_cast<float4*>(out + (size_t)curd * H) + lane;
        asm volatile("red.global.add.v4.f32 [%0], {%1, %2, %3, %4};"
                     :: "l"(o), "f"(acc.x), "f"(acc.y), "f"(acc.z), "f"(acc.w)
                     : "memory");
    }
}

// ---------------------------------------------------------------------------
extern "C" void kernel_launch(void* const* d_in, const int* in_sizes, int n_in,
                              void* d_out, int out_size) {
    const float* x  = (const float*)d_in[0];   // [NV, 128] f32
    const float* W  = (const float*)d_in[1];   // [128, 256] f32
    const int*   ei = (const int*)d_in[2];     // [2, E] i32
    float* out = (float*)d_out;                // [NV, 128] f32

    int nE    = in_sizes[2] / 2;
    int total = in_sizes[2];

    k_zero_cnt<<<(NV + 255) / 256, 256>>>();
    k_hist<<<(total / 4 + 255) / 256, 256>>>(ei, total);
    k_scan<<<1, 1024>>>();
    k_fill<<<(2 * nE + 255) / 256, 256>>>(ei, nE);

    dim3 ggrid((NV + 127) / 128, 2);
    k_gemm<<<ggrid, 256>>>(x, W, out);

    int nwarps = (2 * nE + 7) / 8;
    k_scat_seg<<<(nwarps * 32 + 255) / 256, 256>>>(out, 2 * nE);

    (void)n_in; (void)out_size;
}

// round 17
// speedup vs baseline: 1.9761x; 1.3153x over previous
#include <cuda_runtime.h>
#include <cuda_bf16.h>
#include <cstdint>

#define NV 50000
#define H 128

// Scratch (no cudaMalloc allowed)
__device__ float g_y1[(size_t)NV * H];   // 25.6 MB, x @ W1^T
__device__ int   g_cnt[NV];              // degree

// ---------------------------------------------------------------------------
// 1. zero degree counters
// ---------------------------------------------------------------------------
__global__ void k_zero_cnt() {
    int i = blockIdx.x * blockDim.x + threadIdx.x;
    if (i < NV) g_cnt[i] = 0;
}

// ---------------------------------------------------------------------------
// 2. degree histogram: every element of edge_idx is a dst exactly once
// ---------------------------------------------------------------------------
__global__ void k_hist(const int* __restrict__ ei, int total) {
    int i = blockIdx.x * blockDim.x + threadIdx.x;
    int i4 = i * 4;
    if (i4 + 3 < total) {
        int4 v = *reinterpret_cast<const int4*>(ei + i4);
        atomicAdd(&g_cnt[v.x], 1);
        atomicAdd(&g_cnt[v.y], 1);
        atomicAdd(&g_cnt[v.z], 1);
        atomicAdd(&g_cnt[v.w], 1);
    } else {
        for (int j = i4; j < total; j++) atomicAdd(&g_cnt[ei[j]], 1);
    }
}

// ---------------------------------------------------------------------------
// 3. Merged HMMA GEMM: one 512-thread block computes BOTH halves of
//    Y[128 rows, 256 cols] = x_tile[128,128] @ Wcat^T.
//    A tile loaded + converted ONCE (R12 did it twice, once per grid.y).
//    cols [0,128)   -> g_y1
//    cols [128,256) -> out, scaled by deg(row)
//    Wcat[n][k] = W[(n&127)*256 + ((n>=128)?128:0) + k]
// ---------------------------------------------------------------------------
#define BK 32
#define PITCH 40
// dynamic smem layout (bytes)
#define SM_AHI 0
#define SM_ALO 10240
#define SM_BHI 20480
#define SM_BLO 40960
#define SM_TOT 61440

__device__ __forceinline__ void mma_16816(float* c, const uint32_t* a,
                                          uint32_t b0, uint32_t b1) {
    asm volatile(
        "mma.sync.aligned.m16n8k16.row.col.f32.bf16.bf16.f32 "
        "{%0,%1,%2,%3}, {%4,%5,%6,%7}, {%8,%9}, {%0,%1,%2,%3};"
        : "+f"(c[0]), "+f"(c[1]), "+f"(c[2]), "+f"(c[3])
        : "r"(a[0]), "r"(a[1]), "r"(a[2]), "r"(a[3]), "r"(b0), "r"(b1));
}

#define LDSM_X4(r0, r1, r2, r3, addr) \
    asm volatile("ldmatrix.sync.aligned.m8n8.x4.shared.b16 {%0,%1,%2,%3}, [%4];" \
                 : "=r"(r0), "=r"(r1), "=r"(r2), "=r"(r3) : "r"(addr))

__global__ __launch_bounds__(512, 1)
void k_gemm(const float* __restrict__ x, const float* __restrict__ W,
            float* __restrict__ out) {
    extern __shared__ __align__(16) char smem[];
    __nv_bfloat16* Ahi = reinterpret_cast<__nv_bfloat16*>(smem + SM_AHI);
    __nv_bfloat16* Alo = reinterpret_cast<__nv_bfloat16*>(smem + SM_ALO);
    __nv_bfloat16* Bhi = reinterpret_cast<__nv_bfloat16*>(smem + SM_BHI);
    __nv_bfloat16* Blo = reinterpret_cast<__nv_bfloat16*>(smem + SM_BLO);

    const int tid    = threadIdx.x;
    const int wid    = tid >> 5;
    const int lane   = tid & 31;
    const int grp    = lane >> 2;
    const int tig    = lane & 3;
    const int warp_m = wid & 3;        // 4 warps along M (32 rows each)
    const int warp_n = wid >> 2;       // 4 warps along N (64 cols each, of 256)
    const int row0   = blockIdx.x * 128;

    const uint32_t sAhi = (uint32_t)__cvta_generic_to_shared(Ahi);
    const uint32_t sAlo = (uint32_t)__cvta_generic_to_shared(Alo);
    const uint32_t sBhi = (uint32_t)__cvta_generic_to_shared(Bhi);
    const uint32_t sBlo = (uint32_t)__cvta_generic_to_shared(Blo);

    const int a_row16 = (lane & 7) + ((lane >> 3) & 1) * 8;
    const int a_k8    = ((lane >> 4) & 1) * 8;
    const uint32_t aoff = (uint32_t)(((warp_m * 32 + a_row16) * PITCH + a_k8) * 2);
    const int b_row16 = (lane & 7) + ((lane >> 4) & 1) * 8;
    const int b_k8    = ((lane >> 3) & 1) * 8;
    const uint32_t boff = (uint32_t)(((warp_n * 64 + b_row16) * PITCH + b_k8) * 2);

    float acc[2][8][4];
#pragma unroll
    for (int mi = 0; mi < 2; mi++)
#pragma unroll
        for (int ni = 0; ni < 8; ni++)
#pragma unroll
            for (int q = 0; q < 4; q++) acc[mi][ni][q] = 0.0f;

    for (int kt = 0; kt < 4; kt++) {
        __syncthreads();
        // ---- A tile (128 x 32 fp32 -> hi/lo), 1024 float4 / 512 thr ----
#pragma unroll
        for (int p = 0; p < 2; p++) {
            int idx  = p * 512 + tid;
            int row  = idx >> 3;
            int colq = idx & 7;
            int grow = row0 + row;
            float4 v = make_float4(0.f, 0.f, 0.f, 0.f);
            if (grow < NV)
                v = *reinterpret_cast<const float4*>(
                    x + (size_t)grow * H + kt * BK + colq * 4);
            uint32_t bx = __float_as_uint(v.x), by = __float_as_uint(v.y);
            uint32_t bz = __float_as_uint(v.z), bw = __float_as_uint(v.w);
            uint32_t hp0 = __byte_perm(bx, by, 0x7632);
            uint32_t hp1 = __byte_perm(bz, bw, 0x7632);
            float lx = v.x - __uint_as_float(bx & 0xFFFF0000u);
            float ly = v.y - __uint_as_float(by & 0xFFFF0000u);
            float lz = v.z - __uint_as_float(bz & 0xFFFF0000u);
            float lw = v.w - __uint_as_float(bw & 0xFFFF0000u);
            __nv_bfloat162 l0 = __floats2bfloat162_rn(lx, ly);
            __nv_bfloat162 l1 = __floats2bfloat162_rn(lz, lw);
            *reinterpret_cast<uint2*>(&Ahi[row * PITCH + colq * 4]) =
                make_uint2(hp0, hp1);
            *reinterpret_cast<uint2*>(&Alo[row * PITCH + colq * 4]) =
                make_uint2(*reinterpret_cast<uint32_t*>(&l0),
                           *reinterpret_cast<uint32_t*>(&l1));
        }
        // ---- B tile (256 x 32 fp32 -> hi/lo), 2048 float4 / 512 thr ----
#pragma unroll
        for (int p = 0; p < 4; p++) {
            int idx  = p * 512 + tid;
            int n    = idx >> 3;               // 0..255
            int colq = idx & 7;
            int nc0  = (n >= 128) ? 128 : 0;
            float4 v = *reinterpret_cast<const float4*>(
                W + (size_t)(n & 127) * (2 * H) + nc0 + kt * BK + colq * 4);
            uint32_t bx = __float_as_uint(v.x), by = __float_as_uint(v.y);
            uint32_t bz = __float_as_uint(v.z), bw = __float_as_uint(v.w);
            uint32_t hp0 = __byte_perm(bx, by, 0x7632);
            uint32_t hp1 = __byte_perm(bz, bw, 0x7632);
            float lx = v.x - __uint_as_float(bx & 0xFFFF0000u);
            float ly = v.y - __uint_as_float(by & 0xFFFF0000u);
            float lz = v.z - __uint_as_float(bz & 0xFFFF0000u);
            float lw = v.w - __uint_as_float(bw & 0xFFFF0000u);
            __nv_bfloat162 l0 = __floats2bfloat162_rn(lx, ly);
            __nv_bfloat162 l1 = __floats2bfloat162_rn(lz, lw);
            *reinterpret_cast<uint2*>(&Bhi[n * PITCH + colq * 4]) =
                make_uint2(hp0, hp1);
            *reinterpret_cast<uint2*>(&Blo[n * PITCH + colq * 4]) =
                make_uint2(*reinterpret_cast<uint32_t*>(&l0),
                           *reinterpret_cast<uint32_t*>(&l1));
        }
        __syncthreads();

#pragma unroll
        for (int ks = 0; ks < 2; ks++) {
            const uint32_t koff = (uint32_t)(ks * 16 * 2);
            uint32_t ah[2][4], al[2][4];
#pragma unroll
            for (int mi = 0; mi < 2; mi++) {
                uint32_t ao = aoff + (uint32_t)(mi * 16 * PITCH * 2) + koff;
                LDSM_X4(ah[mi][0], ah[mi][1], ah[mi][2], ah[mi][3], sAhi + ao);
                LDSM_X4(al[mi][0], al[mi][1], al[mi][2], al[mi][3], sAlo + ao);
            }
            // interleave B fragment loads with MMAs (keeps live regs low)
#pragma unroll
            for (int pr = 0; pr < 4; pr++) {
                uint32_t bo = boff + (uint32_t)(pr * 16 * PITCH * 2) + koff;
                uint32_t b00, b01, b10, b11, c00, c01, c10, c11;
                LDSM_X4(b00, b01, b10, b11, sBhi + bo);   // ni=2pr, 2pr+1 (hi)
                LDSM_X4(c00, c01, c10, c11, sBlo + bo);   // ni=2pr, 2pr+1 (lo)
#pragma unroll
                for (int mi = 0; mi < 2; mi++) {
                    mma_16816(acc[mi][pr * 2],     ah[mi], b00, b01);
                    mma_16816(acc[mi][pr * 2],     ah[mi], c00, c01);
                    mma_16816(acc[mi][pr * 2],     al[mi], b00, b01);
                    mma_16816(acc[mi][pr * 2 + 1], ah[mi], b10, b11);
                    mma_16816(acc[mi][pr * 2 + 1], ah[mi], c10, c11);
                    mma_16816(acc[mi][pr * 2 + 1], al[mi], b10, b11);
                }
            }
        }
    }

    // ---- epilogue: warp_n 0,1 -> g_y1; warp_n 2,3 -> out (deg-scaled) ----
    const bool to_out = (warp_n >= 2);
    float* dst = to_out ? out : g_y1;
#pragma unroll
    for (int mi = 0; mi < 2; mi++) {
        int r0 = row0 + warp_m * 32 + mi * 16 + grp;
        float dg0 = 1.0f, dg1 = 1.0f;
        if (to_out) {
            if (r0 < NV)     dg0 = (float)g_cnt[r0];
            if (r0 + 8 < NV) dg1 = (float)g_cnt[r0 + 8];
        }
#pragma unroll
        for (int ni = 0; ni < 8; ni++) {
            int col = warp_n * 64 + ni * 8 + tig * 2;   // 0..255
            int lc  = col - (to_out ? 128 : 0);          // 0..127 in dst
            if (r0 < NV)
                *reinterpret_cast<float2*>(dst + (size_t)r0 * H + lc) =
                    make_float2(acc[mi][ni][0] * dg0, acc[mi][ni][1] * dg0);
            if (r0 + 8 < NV)
                *reinterpret_cast<float2*>(dst + (size_t)(r0 + 8) * H + lc) =
                    make_float2(acc[mi][ni][2] * dg1, acc[mi][ni][3] * dg1);
        }
    }
}

// ---------------------------------------------------------------------------
// 4. scatter (proven R4/R12; at REDG issue floor): warp per directed edge,
//    out[dst] += y1[src] via red.global.add.v4.f32
// ---------------------------------------------------------------------------
__global__ __launch_bounds__(256)
void k_scatter(const int* __restrict__ ei, int nE, float* __restrict__ out) {
    int gw   = (int)(((unsigned)blockIdx.x * blockDim.x + threadIdx.x) >> 5);
    int lane = threadIdx.x & 31;
    if (gw >= 2 * nE) return;

    int s, d;
    if (gw < nE) { s = ei[gw];      d = ei[nE + gw]; }
    else         { int e = gw - nE; d = ei[e]; s = ei[nE + e]; }

    float4 v = reinterpret_cast<const float4*>(g_y1 + (size_t)s * H)[lane];
    float4* o = reinterpret_cast<float4*>(out + (size_t)d * H) + lane;
    asm volatile("red.global.add.v4.f32 [%0], {%1, %2, %3, %4};"
                 :: "l"(o), "f"(v.x), "f"(v.y), "f"(v.z), "f"(v.w)
                 : "memory");
}

// ---------------------------------------------------------------------------
extern "C" void kernel_launch(void* const* d_in, const int* in_sizes, int n_in,
                              void* d_out, int out_size) {
    const float* x  = (const float*)d_in[0];   // [NV, 128] f32
    const float* W  = (const float*)d_in[1];   // [128, 256] f32
    const int*   ei = (const int*)d_in[2];     // [2, E] i32
    float* out = (float*)d_out;                // [NV, 128] f32

    int nE    = in_sizes[2] / 2;
    int total = in_sizes[2];

    cudaFuncSetAttribute(k_gemm,
                         cudaFuncAttributeMaxDynamicSharedMemorySize, SM_TOT);

    k_zero_cnt<<<(NV + 255) / 256, 256>>>();
    k_hist<<<(total / 4 + 255) / 256, 256>>>(ei, total);

    k_gemm<<<(NV + 127) / 128, 512, SM_TOT>>>(x, W, out);

    k_scatter<<<(2 * nE * 32 + 255) / 256, 256>>>(ei, nE, out);

    (void)n_in; (void)out_size;
}